// round 1
// baseline (speedup 1.0000x reference)
#include <cuda_runtime.h>
#include <math.h>
#include <stdint.h>

// ---------------- problem constants ----------------
#define TWO_B 512          // 2*B concatenated embedding rows
#define BHALF 256
#define DDIM  512
#define NCLS  100000
#define SCALE 30.0f
#define COS_M 0.8775825618903728f   // cos(0.5)
#define SIN_M 0.4794255386042030f   // sin(0.5)
#define TH   (-0.8775825618903728f) // cos(pi - 0.5)
#define MMRG  0.2397127693021015f   // sin(pi-0.5)*0.5

// ---------------- tiling ----------------
#define CT   64                       // columns (classes) per CTA
#define KT   16                       // K tile
#define NBLK ((NCLS + CT - 1) / CT)   // 1563

// ---------------- device scratch (static; no runtime alloc) ----------------
__device__ float g_embn[TWO_B * DDIM];       // normalized embeddings
__device__ float g_winv[NCLS];               // 1/||w_c||
__device__ float g_part[NBLK * TWO_B];       // per-CTA row partial exp-sums
__device__ float g_coslab[TWO_B];            // cosine at label column per row

// ============================================================
// Kernel A: normalize the 512 concatenated embedding rows
// ============================================================
__global__ void k_norm_emb(const float* __restrict__ img,
                           const float* __restrict__ prof) {
    int n = blockIdx.x;                       // 0..511
    const float* src = (n < BHALF) ? (img + (size_t)n * DDIM)
                                   : (prof + (size_t)(n - BHALF) * DDIM);
    __shared__ float wsum[8];
    __shared__ float srinv;
    float ss = 0.f;
    for (int d = threadIdx.x; d < DDIM; d += blockDim.x) {
        float v = src[d];
        ss += v * v;
    }
    #pragma unroll
    for (int o = 16; o; o >>= 1) ss += __shfl_xor_sync(0xffffffffu, ss, o);
    if ((threadIdx.x & 31) == 0) wsum[threadIdx.x >> 5] = ss;
    __syncthreads();
    if (threadIdx.x == 0) {
        float t = 0.f;
        #pragma unroll
        for (int w = 0; w < 8; w++) t += wsum[w];
        srinv = rsqrtf(t);
    }
    __syncthreads();
    float rinv = srinv;
    for (int d = threadIdx.x; d < DDIM; d += blockDim.x)
        g_embn[(size_t)n * DDIM + d] = src[d] * rinv;
}

// ============================================================
// Kernel W: weight row inverse norms (one warp per class row)
// ============================================================
__global__ void k_wnorm(const float* __restrict__ weight) {
    int warp = (blockIdx.x * blockDim.x + threadIdx.x) >> 5;
    int lane = threadIdx.x & 31;
    if (warp >= NCLS) return;
    const float4* wr = (const float4*)(weight + (size_t)warp * DDIM);
    float ss = 0.f;
    #pragma unroll
    for (int t = 0; t < 4; t++) {
        float4 v = wr[lane + t * 32];
        ss += v.x * v.x + v.y * v.y + v.z * v.z + v.w * v.w;
    }
    #pragma unroll
    for (int o = 16; o; o >>= 1) ss += __shfl_xor_sync(0xffffffffu, ss, o);
    if (lane == 0) g_winv[warp] = rsqrtf(ss);
}

// ============================================================
// Kernel B: fused cosine GEMM + exp row-sum partials + label gather
//   CTA tile: 512 rows x 64 cols, K-loop over 512 in steps of 16.
//   512 threads, each computes an 8x8 micro-tile.
// ============================================================
__global__ __launch_bounds__(512, 1)
void k_main(const float* __restrict__ weight,
            const long long* __restrict__ label) {
    __shared__ float sE[TWO_B][KT + 1];   // [row][kk], +1 pad
    __shared__ float sW[CT][KT + 1];      // [col][kk] (pre-scaled by winv)
    __shared__ float sRow[TWO_B];

    const int tid  = threadIdx.x;
    const int col0 = blockIdx.x * CT;
    const int cg   = tid & 7;     // col group (8 cols each)
    const int rg   = tid >> 3;    // row group (8 rows each), 0..63

    float acc[8][8];
    #pragma unroll
    for (int i = 0; i < 8; i++)
        #pragma unroll
        for (int j = 0; j < 8; j++) acc[i][j] = 0.f;

    for (int k0 = 0; k0 < DDIM; k0 += KT) {
        __syncthreads();   // previous compute done before overwriting tiles

        // load sE: 2048 float4 by 512 threads (4 each)
        #pragma unroll
        for (int t = 0; t < 4; t++) {
            int e4  = t * 512 + tid;          // 0..2047
            int n   = e4 >> 2;                // 0..511
            int kk4 = (e4 & 3) * 4;           // 0,4,8,12
            float4 v = *(const float4*)&g_embn[(size_t)n * DDIM + k0 + kk4];
            sE[n][kk4 + 0] = v.x;
            sE[n][kk4 + 1] = v.y;
            sE[n][kk4 + 2] = v.z;
            sE[n][kk4 + 3] = v.w;
        }
        // load sW: 256 float4 by first 256 threads, pre-scaled by winv
        if (tid < 256) {
            int c   = tid >> 2;               // 0..63
            int kk4 = (tid & 3) * 4;
            int gc  = col0 + c;
            float4 v;
            float wi = 0.f;
            if (gc < NCLS) {
                v  = *(const float4*)&weight[(size_t)gc * DDIM + k0 + kk4];
                wi = g_winv[gc];
            } else {
                v = make_float4(0.f, 0.f, 0.f, 0.f);
            }
            sW[c][kk4 + 0] = v.x * wi;
            sW[c][kk4 + 1] = v.y * wi;
            sW[c][kk4 + 2] = v.z * wi;
            sW[c][kk4 + 3] = v.w * wi;
        }
        __syncthreads();

        #pragma unroll
        for (int kk = 0; kk < KT; kk++) {
            float a[8], b[8];
            #pragma unroll
            for (int i = 0; i < 8; i++) a[i] = sE[rg * 8 + i][kk];
            #pragma unroll
            for (int j = 0; j < 8; j++) b[j] = sW[cg * 8 + j][kk];
            #pragma unroll
            for (int i = 0; i < 8; i++)
                #pragma unroll
                for (int j = 0; j < 8; j++)
                    acc[i][j] = fmaf(a[i], b[j], acc[i][j]);
        }
    }

    // ---------------- epilogue ----------------
    __syncthreads();
    sRow[tid] = 0.f;
    __syncthreads();

    #pragma unroll
    for (int i = 0; i < 8; i++) {
        int n   = rg * 8 + i;                        // global row
        int lab = (int)label[n & 255];
        float rowpart = 0.f;
        #pragma unroll
        for (int j = 0; j < 8; j++) {
            int c = col0 + cg * 8 + j;
            if (c < NCLS) {
                float cosv = acc[i][j];              // already normalized
                rowpart += expf(SCALE * cosv);
                if (c == lab) g_coslab[n] = cosv;    // unique writer
            }
        }
        atomicAdd(&sRow[n], rowpart);
    }
    __syncthreads();
    g_part[(size_t)blockIdx.x * TWO_B + tid] = sRow[tid];
}

// ============================================================
// Kernel C: deterministic cross-CTA reduction + margin + mean NLL
// ============================================================
__global__ void k_final(const long long* __restrict__ label,
                        float* __restrict__ out) {
    int n = threadIdx.x;   // 512 threads, one per row
    float s = 0.f;
    for (int b = 0; b < NBLK; b++) s += g_part[(size_t)b * TWO_B + n];

    float cosl = g_coslab[n];
    float sine = sqrtf(fminf(fmaxf(1.f - cosl * cosl, 0.f), 1.f));
    float phi  = cosl * COS_M - sine * SIN_M;
    if (!(cosl > TH)) phi = cosl - MMRG;

    float total = s - expf(SCALE * cosl) + expf(SCALE * phi);
    float nll   = logf(total) - SCALE * phi;

    // block mean over 512 values
    __shared__ float wsum[16];
    float v = nll;
    #pragma unroll
    for (int o = 16; o; o >>= 1) v += __shfl_xor_sync(0xffffffffu, v, o);
    if ((n & 31) == 0) wsum[n >> 5] = v;
    __syncthreads();
    if (n == 0) {
        float t = 0.f;
        #pragma unroll
        for (int w = 0; w < 16; w++) t += wsum[w];
        out[0] = t / (float)TWO_B;
    }
}

// ============================================================
// launch
// ============================================================
extern "C" void kernel_launch(void* const* d_in, const int* in_sizes, int n_in,
                              void* d_out, int out_size) {
    const float*     img  = (const float*)d_in[0];
    const float*     prof = (const float*)d_in[1];
    const float*     w    = (const float*)d_in[2];
    const long long* lab  = (const long long*)d_in[3];
    float* out = (float*)d_out;

    k_norm_emb<<<TWO_B, 256>>>(img, prof);
    k_wnorm<<<(NCLS * 32 + 255) / 256, 256>>>(w);
    k_main<<<NBLK, 512>>>(w, lab);
    k_final<<<1, TWO_B>>>(lab, out);
}

// round 3
// speedup vs baseline: 5.1224x; 5.1224x over previous
#include <cuda_runtime.h>
#include <math.h>
#include <stdint.h>

// ---------------- problem constants ----------------
#define TWO_B 512
#define BHALF 256
#define DDIM  512
#define NCLS  100000
#define SCALE 30.0f
#define S_LOG2E 43.280851226668914f  // 30 * log2(e)
#define COS_M 0.8775825618903728f
#define SIN_M 0.4794255386042030f
#define TH   (-0.8775825618903728f)
#define MMRG  0.2397127693021015f

// ---------------- GEMM tiling ----------------
#define MT      128                   // rows per CTA
#define NT      256                   // classes per CTA
#define NTILES  391                   // ceil(NCLS/NT)
#define NPART   392
#define KC      32                    // K floats per chunk
#define NCHUNK  16
#define NSTAGE  3
#define STRIDEF 36                    // padded floats per row (bank-conflict-free)

// smem layout (floats)
#define SA_F    0
#define SA_STG  (MT * STRIDEF)                 // 4608 floats / stage
#define SB_F    (NSTAGE * SA_STG)              // 13824
#define SB_STG  (NT * STRIDEF)                 // 9216 floats / stage
#define WS_F    (SB_F + NSTAGE * SB_STG)       // 41472
#define SR_F    (WS_F + NT)                    // 41728 : sRowP[4][128]
#define SMEM_F  (SR_F + 4 * MT)                // 42240 floats
#define SMEM_BYTES (SMEM_F * 4)                // 168960 B

// ---------------- device scratch ----------------
__device__ float g_embn[TWO_B * DDIM];
__device__ float g_part[TWO_B * NPART];
__device__ float g_coslab[TWO_B];
__device__ float g_nll[TWO_B];

// ---------------- helpers ----------------
__device__ __forceinline__ uint32_t smem_u32(const void* p) {
    uint32_t a;
    asm("{ .reg .u64 t; cvta.to.shared.u64 t, %1; cvt.u32.u64 %0, t; }" : "=r"(a) : "l"(p));
    return a;
}
__device__ __forceinline__ void cp16(uint32_t dst, const void* src) {
    asm volatile("cp.async.cg.shared.global [%0], [%1], 16;" :: "r"(dst), "l"(src));
}
__device__ __forceinline__ void cp_commit() { asm volatile("cp.async.commit_group;"); }
__device__ __forceinline__ void cp_wait1()  { asm volatile("cp.async.wait_group 1;"); }

__device__ __forceinline__ uint32_t f2tf32(float x) {
    uint32_t u; asm("cvt.rna.tf32.f32 %0, %1;" : "=r"(u) : "f"(x)); return u;
}
__device__ __forceinline__ void mma_tf32(float* d, const uint32_t* a, const uint32_t* b) {
    asm volatile(
        "mma.sync.aligned.m16n8k8.row.col.f32.tf32.tf32.f32 "
        "{%0,%1,%2,%3}, {%4,%5,%6,%7}, {%8,%9}, {%0,%1,%2,%3};"
        : "+f"(d[0]), "+f"(d[1]), "+f"(d[2]), "+f"(d[3])
        : "r"(a[0]), "r"(a[1]), "r"(a[2]), "r"(a[3]), "r"(b[0]), "r"(b[1]));
}

// ============================================================
// Kernel A: normalize embeddings, round to tf32
// ============================================================
__global__ void k_norm_emb(const float* __restrict__ img,
                           const float* __restrict__ prof) {
    int n = blockIdx.x;
    const float* src = (n < BHALF) ? (img + (size_t)n * DDIM)
                                   : (prof + (size_t)(n - BHALF) * DDIM);
    __shared__ float wsum[8];
    __shared__ float srinv;
    float ss = 0.f;
    for (int d = threadIdx.x; d < DDIM; d += blockDim.x) {
        float v = src[d];
        ss += v * v;
    }
    #pragma unroll
    for (int o = 16; o; o >>= 1) ss += __shfl_xor_sync(0xffffffffu, ss, o);
    if ((threadIdx.x & 31) == 0) wsum[threadIdx.x >> 5] = ss;
    __syncthreads();
    if (threadIdx.x == 0) {
        float t = 0.f;
        #pragma unroll
        for (int w = 0; w < 8; w++) t += wsum[w];
        srinv = rsqrtf(t);
    }
    __syncthreads();
    float rinv = srinv;
    for (int d = threadIdx.x; d < DDIM; d += blockDim.x) {
        float v = src[d] * rinv;
        g_embn[(size_t)n * DDIM + d] = __uint_as_float(f2tf32(v));
    }
}

// ============================================================
// Kernel B: tf32 mma.sync GEMM + fused norm + exp epilogue
//   CTA 128 rows x 256 classes, 512 threads (warps 4M x 4N).
// ============================================================
__global__ void __launch_bounds__(512, 1)
k_main(const float* __restrict__ weight, const long long* __restrict__ label) {
    extern __shared__ float smf[];
    const uint32_t sb = smem_u32(smf);
    const int tid   = threadIdx.x;
    const int lane  = tid & 31;
    const int wrp   = tid >> 5;
    const int warpM = wrp & 3;     // 0..3
    const int warpN = wrp >> 2;    // 0..3
    const int g     = lane >> 2;   // 0..7
    const int tig   = lane & 3;    // 0..3

    const int m0   = blockIdx.x * MT;      // row offset (0,128,256,384)
    const int col0 = blockIdx.y * NT;      // class offset

    float acc[2][8][4];
    #pragma unroll
    for (int mt = 0; mt < 2; mt++)
        #pragma unroll
        for (int nt = 0; nt < 8; nt++)
            #pragma unroll
            for (int e = 0; e < 4; e++) acc[mt][nt][e] = 0.f;

    // ---- chunk loader ----
    auto load_chunk = [&](int c, int st) {
        // A: 128 rows x 32 floats = 1024 float4
        uint32_t abase = sb + (uint32_t)(SA_F + st * SA_STG) * 4u;
        const float* eb = g_embn + (size_t)m0 * DDIM + c * KC;
        #pragma unroll
        for (int i = 0; i < 2; i++) {
            int idx = i * 512 + tid;
            int r = idx >> 3, j = idx & 7;
            cp16(abase + (uint32_t)(r * STRIDEF * 4 + j * 16),
                 eb + (size_t)r * DDIM + j * 4);
        }
        // B: 256 class rows x 32 floats = 2048 float4
        uint32_t bbase = sb + (uint32_t)(SB_F + st * SB_STG) * 4u;
        #pragma unroll
        for (int i = 0; i < 4; i++) {
            int idx = i * 512 + tid;
            int r = idx >> 3, j = idx & 7;
            int crow = col0 + r; if (crow >= NCLS) crow = NCLS - 1;
            cp16(bbase + (uint32_t)(r * STRIDEF * 4 + j * 16),
                 weight + (size_t)crow * DDIM + c * KC + j * 4);
        }
    };

    load_chunk(0, 0); cp_commit();
    load_chunk(1, 1); cp_commit();

    float wsq = 0.f;                       // fused weight sumsq (class tid/2, half tid&1)
    const int sqn = tid >> 1, sqk = (tid & 1) * 16;

    for (int c = 0; c < NCHUNK; c++) {
        const int st = c % NSTAGE;
        cp_wait1();
        __syncthreads();
        if (c + 2 < NCHUNK) load_chunk(c + 2, (c + 2) % NSTAGE);
        cp_commit();

        const float* sA = smf + SA_F + st * SA_STG;
        const float* sB = smf + SB_F + st * SB_STG;

        // fused sumsq over raw fp32 B tile
        #pragma unroll
        for (int j = 0; j < 4; j++) {
            const float4 v = *(const float4*)(sB + sqn * STRIDEF + sqk + j * 4);
            wsq = fmaf(v.x, v.x, fmaf(v.y, v.y, fmaf(v.z, v.z, fmaf(v.w, v.w, wsq))));
        }

        // 4 k-steps of 8
        #pragma unroll
        for (int ks = 0; ks < 4; ks++) {
            const int k0 = ks * 8;
            uint32_t a[2][4];
            #pragma unroll
            for (int mt = 0; mt < 2; mt++) {
                const float* p = sA + (warpM * 32 + mt * 16 + g) * STRIDEF + k0;
                a[mt][0] = __float_as_uint(p[tig]);
                a[mt][1] = __float_as_uint(p[8 * STRIDEF + tig]);
                a[mt][2] = __float_as_uint(p[tig + 4]);
                a[mt][3] = __float_as_uint(p[8 * STRIDEF + tig + 4]);
            }
            uint32_t b[8][2];
            #pragma unroll
            for (int nt = 0; nt < 8; nt++) {
                const float* p = sB + (warpN * 64 + nt * 8 + g) * STRIDEF + k0;
                b[nt][0] = f2tf32(p[tig]);
                b[nt][1] = f2tf32(p[tig + 4]);
            }
            #pragma unroll
            for (int mt = 0; mt < 2; mt++)
                #pragma unroll
                for (int nt = 0; nt < 8; nt++)
                    mma_tf32(acc[mt][nt], a[mt], b[nt]);
        }
    }

    // winv
    {
        float o = __shfl_xor_sync(0xffffffffu, wsq, 1);
        if ((tid & 1) == 0) smf[WS_F + sqn] = rsqrtf(wsq + o);
    }
    __syncthreads();

    // ---- epilogue: exp row-sums + label gather ----
    const float* s_winv = smf + WS_F;
    float* sRowP = smf + SR_F;           // [4 warpN][128 rows]

    #pragma unroll
    for (int mt = 0; mt < 2; mt++) {
        const int lrow0 = warpM * 32 + mt * 16 + g;
        const int grow0 = m0 + lrow0;
        const int grow1 = grow0 + 8;
        const int lab0 = (int)label[grow0 & 255];
        const int lab1 = (int)label[grow1 & 255];
        float sum0 = 0.f, sum1 = 0.f;
        #pragma unroll
        for (int nt = 0; nt < 8; nt++) {
            #pragma unroll
            for (int e = 0; e < 2; e++) {
                const int cl = warpN * 64 + nt * 8 + tig * 2 + e;
                const int cc = col0 + cl;
                const float wi = s_winv[cl];
                const float c0 = acc[mt][nt][e]     * wi;
                const float c1 = acc[mt][nt][2 + e] * wi;
                if (cc < NCLS) {
                    sum0 += exp2f(c0 * S_LOG2E);
                    sum1 += exp2f(c1 * S_LOG2E);
                    if (cc == lab0) g_coslab[grow0] = c0;
                    if (cc == lab1) g_coslab[grow1] = c1;
                }
            }
        }
        sum0 += __shfl_xor_sync(0xffffffffu, sum0, 1);
        sum0 += __shfl_xor_sync(0xffffffffu, sum0, 2);
        sum1 += __shfl_xor_sync(0xffffffffu, sum1, 1);
        sum1 += __shfl_xor_sync(0xffffffffu, sum1, 2);
        if (tig == 0) {
            sRowP[warpN * MT + lrow0]     = sum0;
            sRowP[warpN * MT + lrow0 + 8] = sum1;
        }
    }
    __syncthreads();
    if (tid < MT) {
        float s = sRowP[tid] + sRowP[MT + tid] + sRowP[2 * MT + tid] + sRowP[3 * MT + tid];
        g_part[(size_t)(m0 + tid) * NPART + blockIdx.y] = s;
    }
}

// ============================================================
// Kernel C1: per-row reduce + margin
// ============================================================
__global__ void k_final1(void) {
    int n = blockIdx.x;
    float s = 0.f;
    for (int t = threadIdx.x; t < NTILES; t += 128)
        s += g_part[(size_t)n * NPART + t];
    __shared__ float wsum[4];
    #pragma unroll
    for (int o = 16; o; o >>= 1) s += __shfl_xor_sync(0xffffffffu, s, o);
    if ((threadIdx.x & 31) == 0) wsum[threadIdx.x >> 5] = s;
    __syncthreads();
    if (threadIdx.x == 0) {
        float tot = wsum[0] + wsum[1] + wsum[2] + wsum[3];
        float cosl = g_coslab[n];
        float sine = sqrtf(fminf(fmaxf(1.f - cosl * cosl, 0.f), 1.f));
        float phi = cosl * COS_M - sine * SIN_M;
        if (!(cosl > TH)) phi = cosl - MMRG;
        float total = tot - exp2f(cosl * S_LOG2E) + exp2f(phi * S_LOG2E);
        g_nll[n] = logf(total) - SCALE * phi;
    }
}

// ============================================================
// Kernel C2: mean
// ============================================================
__global__ void k_final2(float* __restrict__ out) {
    int n = threadIdx.x;
    float v = g_nll[n];
    __shared__ float wsum[16];
    #pragma unroll
    for (int o = 16; o; o >>= 1) v += __shfl_xor_sync(0xffffffffu, v, o);
    if ((n & 31) == 0) wsum[n >> 5] = v;
    __syncthreads();
    if (n == 0) {
        float t = 0.f;
        #pragma unroll
        for (int w = 0; w < 16; w++) t += wsum[w];
        out[0] = t / (float)TWO_B;
    }
}

// ============================================================
// launch
// ============================================================
extern "C" void kernel_launch(void* const* d_in, const int* in_sizes, int n_in,
                              void* d_out, int out_size) {
    const float*     img  = (const float*)d_in[0];
    const float*     prof = (const float*)d_in[1];
    const float*     w    = (const float*)d_in[2];
    const long long* lab  = (const long long*)d_in[3];
    float* out = (float*)d_out;

    cudaFuncSetAttribute(k_main, cudaFuncAttributeMaxDynamicSharedMemorySize, SMEM_BYTES);

    k_norm_emb<<<TWO_B, 256>>>(img, prof);
    dim3 grid(4, NTILES);                 // M fastest -> weight L2 reuse
    k_main<<<grid, 512, SMEM_BYTES>>>(w, lab);
    k_final1<<<TWO_B, 128>>>();
    k_final2<<<1, TWO_B>>>(out);
}

// round 4
// speedup vs baseline: 7.8498x; 1.5324x over previous
#include <cuda_runtime.h>
#include <math.h>
#include <stdint.h>

// ---------------- problem constants ----------------
#define TWO_B 512
#define BHALF 256
#define DDIM  512
#define NCLS  100000
#define SCALE 30.0f
#define S_LOG2E 43.280851226668914f  // 30 * log2(e)
#define COS_M 0.8775825618903728f
#define SIN_M 0.4794255386042030f
#define TH   (-0.8775825618903728f)
#define MMRG  0.2397127693021015f

// ---------------- GEMM tiling ----------------
#define MT      128                   // rows per CTA
#define NT      256                   // classes per CTA
#define NTILES  391                   // ceil(NCLS/NT)
#define NPART   392
#define KC      32                    // K halves per chunk (64 B/row)
#define NCHUNK  16
#define NSTAGE  4
#define ROWB    80                    // padded bytes per smem row (conflict-free)

// smem layout (bytes)
#define A_OFF   0
#define A_STG   (MT * ROWB)                    // 10240
#define B_OFF   (NSTAGE * A_STG)               // 40960
#define B_STG   (NT * ROWB)                    // 20480
#define SR_OFF  (B_OFF + NSTAGE * B_STG)       // 122880 : sRowP[4][128] floats
#define SMEM_BYTES (SR_OFF + 4 * MT * 4)       // 124928

// ---------------- device scratch ----------------
__device__ __align__(16) uint16_t g_embn[TWO_B * DDIM];     // normalized emb, bf16
__device__ __align__(16) uint16_t g_wn[(size_t)NCLS * DDIM];// normalized weight, bf16
__device__ float g_part[TWO_B * NPART];
__device__ float g_coslab[TWO_B];
__device__ float g_nll[TWO_B];

// ---------------- helpers ----------------
__device__ __forceinline__ uint32_t smem_u32(const void* p) {
    uint32_t a;
    asm("{ .reg .u64 t; cvta.to.shared.u64 t, %1; cvt.u32.u64 %0, t; }" : "=r"(a) : "l"(p));
    return a;
}
__device__ __forceinline__ void cp16(uint32_t dst, const void* src) {
    asm volatile("cp.async.cg.shared.global [%0], [%1], 16;" :: "r"(dst), "l"(src));
}
__device__ __forceinline__ void cp_commit() { asm volatile("cp.async.commit_group;"); }
__device__ __forceinline__ void cp_wait2()  { asm volatile("cp.async.wait_group 2;"); }

__device__ __forceinline__ uint32_t pack_bf16x2(float lo, float hi) {
    uint32_t r;
    asm("cvt.rn.bf16x2.f32 %0, %1, %2;" : "=r"(r) : "f"(hi), "f"(lo));
    return r;
}
__device__ __forceinline__ void ldm_x4(uint32_t* r, uint32_t addr) {
    asm volatile("ldmatrix.sync.aligned.m8n8.x4.shared.b16 {%0,%1,%2,%3}, [%4];"
                 : "=r"(r[0]), "=r"(r[1]), "=r"(r[2]), "=r"(r[3]) : "r"(addr));
}
__device__ __forceinline__ void mma_bf16(float* d, const uint32_t* a, const uint32_t* b) {
    asm volatile(
        "mma.sync.aligned.m16n8k16.row.col.f32.bf16.bf16.f32 "
        "{%0,%1,%2,%3}, {%4,%5,%6,%7}, {%8,%9}, {%0,%1,%2,%3};"
        : "+f"(d[0]), "+f"(d[1]), "+f"(d[2]), "+f"(d[3])
        : "r"(a[0]), "r"(a[1]), "r"(a[2]), "r"(a[3]), "r"(b[0]), "r"(b[1]));
}

// ============================================================
// Kernel A: normalize embeddings -> bf16
// ============================================================
__global__ void k_norm_emb(const float* __restrict__ img,
                           const float* __restrict__ prof) {
    int n = blockIdx.x;
    const float* src = (n < BHALF) ? (img + (size_t)n * DDIM)
                                   : (prof + (size_t)(n - BHALF) * DDIM);
    __shared__ float wsum[8];
    __shared__ float srinv;
    float ss = 0.f;
    for (int d = threadIdx.x; d < DDIM; d += blockDim.x) {
        float v = src[d];
        ss += v * v;
    }
    #pragma unroll
    for (int o = 16; o; o >>= 1) ss += __shfl_xor_sync(0xffffffffu, ss, o);
    if ((threadIdx.x & 31) == 0) wsum[threadIdx.x >> 5] = ss;
    __syncthreads();
    if (threadIdx.x == 0) {
        float t = 0.f;
        #pragma unroll
        for (int w = 0; w < 8; w++) t += wsum[w];
        srinv = rsqrtf(t);
    }
    __syncthreads();
    float rinv = srinv;
    // 256 threads, each writes 2 bf16x2 pairs (DDIM/4 = 128 pairs... 2 per thread)
    for (int p = threadIdx.x; p < DDIM / 2; p += blockDim.x) {
        float a = src[p * 2] * rinv, b = src[p * 2 + 1] * rinv;
        ((uint32_t*)g_embn)[(size_t)n * (DDIM / 2) + p] = pack_bf16x2(a, b);
    }
}

// ============================================================
// Kernel W: normalize weight rows -> bf16 (one warp per class)
// ============================================================
__global__ void __launch_bounds__(256)
k_wprep(const float* __restrict__ weight) {
    int row = blockIdx.x * 8 + (threadIdx.x >> 5);
    int lane = threadIdx.x & 31;
    if (row >= NCLS) return;
    const float4* src = (const float4*)(weight + (size_t)row * DDIM);
    float4 v[4];
    float ss = 0.f;
    #pragma unroll
    for (int t = 0; t < 4; t++) {
        v[t] = src[lane * 4 + t];                    // lane owns floats 16*lane..+15
        ss = fmaf(v[t].x, v[t].x, fmaf(v[t].y, v[t].y,
             fmaf(v[t].z, v[t].z, fmaf(v[t].w, v[t].w, ss))));
    }
    #pragma unroll
    for (int o = 16; o; o >>= 1) ss += __shfl_xor_sync(0xffffffffu, ss, o);
    float rinv = rsqrtf(ss);
    uint4 out[2];
    uint32_t* ou = (uint32_t*)out;
    #pragma unroll
    for (int t = 0; t < 4; t++) {
        ou[t * 2 + 0] = pack_bf16x2(v[t].x * rinv, v[t].y * rinv);
        ou[t * 2 + 1] = pack_bf16x2(v[t].z * rinv, v[t].w * rinv);
    }
    uint4* dst = (uint4*)(g_wn + (size_t)row * DDIM);
    dst[lane * 2 + 0] = out[0];
    dst[lane * 2 + 1] = out[1];
}

// ============================================================
// Kernel B: bf16 mma.sync GEMM + exp epilogue
//   CTA 128 rows x 256 classes, 512 threads (warps 4M x 4N).
// ============================================================
__global__ void __launch_bounds__(512, 1)
k_main(const long long* __restrict__ label) {
    extern __shared__ char smem[];
    const uint32_t sb = smem_u32(smem);
    const int tid   = threadIdx.x;
    const int lane  = tid & 31;
    const int wrp   = tid >> 5;
    const int warpM = wrp & 3;
    const int warpN = wrp >> 2;
    const int g     = lane >> 2;
    const int tig   = lane & 3;

    const int m0   = blockIdx.x * MT;
    const int col0 = blockIdx.y * NT;

    float acc[2][8][4];
    #pragma unroll
    for (int mt = 0; mt < 2; mt++)
        #pragma unroll
        for (int nt = 0; nt < 8; nt++)
            #pragma unroll
            for (int e = 0; e < 4; e++) acc[mt][nt][e] = 0.f;

    // per-lane ldmatrix offsets (bytes, within a stage)
    const uint32_t a_lo = (uint32_t)((warpM * 32 + (lane & 15)) * ROWB + (lane >> 4) * 16);
    const uint32_t b_lo = (uint32_t)((warpN * 64 + (lane & 7) + ((lane >> 4) << 3)) * ROWB
                                     + (((lane >> 3) & 1) << 4));

    // ---- chunk loader (bf16 rows: 64B = 4 x cp16) ----
    auto load_chunk = [&](int c, int st) {
        // A: 128 rows x 4 segs = 512 cp16
        {
            int r = tid >> 2, j = tid & 3;
            uint32_t dst = sb + A_OFF + (uint32_t)st * A_STG + (uint32_t)(r * ROWB + j * 16);
            cp16(dst, g_embn + (size_t)(m0 + r) * DDIM + c * KC + j * 8);
        }
        // B: 256 rows x 4 segs = 1024 cp16
        #pragma unroll
        for (int i = 0; i < 2; i++) {
            int idx = i * 512 + tid;
            int r = idx >> 2, j = idx & 3;
            int crow = col0 + r; if (crow >= NCLS) crow = NCLS - 1;
            uint32_t dst = sb + B_OFF + (uint32_t)st * B_STG + (uint32_t)(r * ROWB + j * 16);
            cp16(dst, g_wn + (size_t)crow * DDIM + c * KC + j * 8);
        }
    };

    load_chunk(0, 0); cp_commit();
    load_chunk(1, 1); cp_commit();
    load_chunk(2, 2); cp_commit();

    for (int c = 0; c < NCHUNK; c++) {
        const int st = c & 3;
        cp_wait2();
        __syncthreads();
        if (c + 3 < NCHUNK) load_chunk(c + 3, (c + 3) & 3);
        cp_commit();

        const uint32_t aB = sb + A_OFF + (uint32_t)st * A_STG + a_lo;
        const uint32_t bB = sb + B_OFF + (uint32_t)st * B_STG + b_lo;

        #pragma unroll
        for (int ks = 0; ks < 2; ks++) {
            uint32_t aF[2][4];
            ldm_x4(aF[0], aB + ks * 32);
            ldm_x4(aF[1], aB + ks * 32 + 16 * ROWB);
            uint32_t bF[4][4];
            #pragma unroll
            for (int p = 0; p < 4; p++)
                ldm_x4(bF[p], bB + ks * 32 + (uint32_t)p * 16 * ROWB);
            #pragma unroll
            for (int mt = 0; mt < 2; mt++)
                #pragma unroll
                for (int nt = 0; nt < 8; nt++)
                    mma_bf16(acc[mt][nt], aF[mt], &bF[nt >> 1][(nt & 1) * 2]);
        }
    }
    __syncthreads();

    // ---- epilogue: exp row-sums + label gather (cos = acc directly) ----
    float* sRowP = (float*)(smem + SR_OFF);

    #pragma unroll
    for (int mt = 0; mt < 2; mt++) {
        const int lrow0 = warpM * 32 + mt * 16 + g;
        const int grow0 = m0 + lrow0;
        const int grow1 = grow0 + 8;
        const int lab0 = (int)label[grow0 & 255];
        const int lab1 = (int)label[grow1 & 255];
        float sum0 = 0.f, sum1 = 0.f;
        #pragma unroll
        for (int nt = 0; nt < 8; nt++) {
            #pragma unroll
            for (int e = 0; e < 2; e++) {
                const int cc = col0 + warpN * 64 + nt * 8 + tig * 2 + e;
                const float c0 = acc[mt][nt][e];
                const float c1 = acc[mt][nt][2 + e];
                if (cc < NCLS) {
                    sum0 += exp2f(c0 * S_LOG2E);
                    sum1 += exp2f(c1 * S_LOG2E);
                    if (cc == lab0) g_coslab[grow0] = c0;
                    if (cc == lab1) g_coslab[grow1] = c1;
                }
            }
        }
        sum0 += __shfl_xor_sync(0xffffffffu, sum0, 1);
        sum0 += __shfl_xor_sync(0xffffffffu, sum0, 2);
        sum1 += __shfl_xor_sync(0xffffffffu, sum1, 1);
        sum1 += __shfl_xor_sync(0xffffffffu, sum1, 2);
        if (tig == 0) {
            sRowP[warpN * MT + lrow0]     = sum0;
            sRowP[warpN * MT + lrow0 + 8] = sum1;
        }
    }
    __syncthreads();
    if (tid < MT) {
        float s = sRowP[tid] + sRowP[MT + tid] + sRowP[2 * MT + tid] + sRowP[3 * MT + tid];
        g_part[(size_t)(m0 + tid) * NPART + blockIdx.y] = s;
    }
}

// ============================================================
// Kernel C1: per-row reduce + margin
// ============================================================
__global__ void k_final1(void) {
    int n = blockIdx.x;
    float s = 0.f;
    for (int t = threadIdx.x; t < NTILES; t += 128)
        s += g_part[(size_t)n * NPART + t];
    __shared__ float wsum[4];
    #pragma unroll
    for (int o = 16; o; o >>= 1) s += __shfl_xor_sync(0xffffffffu, s, o);
    if ((threadIdx.x & 31) == 0) wsum[threadIdx.x >> 5] = s;
    __syncthreads();
    if (threadIdx.x == 0) {
        float tot = wsum[0] + wsum[1] + wsum[2] + wsum[3];
        float cosl = g_coslab[n];
        float sine = sqrtf(fminf(fmaxf(1.f - cosl * cosl, 0.f), 1.f));
        float phi = cosl * COS_M - sine * SIN_M;
        if (!(cosl > TH)) phi = cosl - MMRG;
        float total = tot - exp2f(cosl * S_LOG2E) + exp2f(phi * S_LOG2E);
        g_nll[n] = logf(total) - SCALE * phi;
    }
}

// ============================================================
// Kernel C2: mean
// ============================================================
__global__ void k_final2(float* __restrict__ out) {
    int n = threadIdx.x;
    float v = g_nll[n];
    __shared__ float wsum[16];
    #pragma unroll
    for (int o = 16; o; o >>= 1) v += __shfl_xor_sync(0xffffffffu, v, o);
    if ((n & 31) == 0) wsum[n >> 5] = v;
    __syncthreads();
    if (n == 0) {
        float t = 0.f;
        #pragma unroll
        for (int w = 0; w < 16; w++) t += wsum[w];
        out[0] = t / (float)TWO_B;
    }
}

// ============================================================
// launch
// ============================================================
extern "C" void kernel_launch(void* const* d_in, const int* in_sizes, int n_in,
                              void* d_out, int out_size) {
    const float*     img  = (const float*)d_in[0];
    const float*     prof = (const float*)d_in[1];
    const float*     w    = (const float*)d_in[2];
    const long long* lab  = (const long long*)d_in[3];
    float* out = (float*)d_out;

    cudaFuncSetAttribute(k_main, cudaFuncAttributeMaxDynamicSharedMemorySize, SMEM_BYTES);

    k_norm_emb<<<TWO_B, 256>>>(img, prof);
    k_wprep<<<(NCLS + 7) / 8, 256>>>(w);
    dim3 grid(4, NTILES);                 // M fastest -> weight L2 reuse
    k_main<<<grid, 512, SMEM_BYTES>>>(lab);
    k_final1<<<TWO_B, 128>>>();
    k_final2<<<1, TWO_B>>>(out);
}